// round 12
// baseline (speedup 1.0000x reference)
#include <cuda_runtime.h>
#include <cuda_fp16.h>
#include <cstdint>

#define D      256
#define BOOK   8192
#define NTOT   16384
#define HW     1024
#define MT     128              // queries per CTA
#define NT     128              // codes per chunk
#define KPHYS  512              // dedup split storage: [z1|z2], [e1|e2]
#define SLICES 6                // logical slices per chunk
#define CHUNKS (BOOK / NT)      // 64
#define GTOT   (CHUNKS * SLICES) // 384

#define A_BYTES (8 * 32 * 32 * 16)            // 131072: [mt(8)][pkt(32)][lane(32)][16B]
#define B_BYTES (NT * 256)                    // 32768 per buffer (128 rows x 256B)
#define STAGES  3
#define DYN_SMEM (A_BYTES + STAGES * B_BYTES) // 229376

__device__ __half g_ecat[BOOK][KPHYS];   // [e1 | e2]
__device__ __half g_zcat[NTOT][KPHYS];   // [z1 | z2]
__device__ float  g_enorm[BOOK];

// ---------------- prep: codebook split + norms ----------------
__global__ void __launch_bounds__(64) eprep_kernel(const float* __restrict__ cb) {
    int c = blockIdx.x, t = threadIdx.x;
    float4 v = reinterpret_cast<const float4*>(cb + (size_t)c * D)[t];
    float f[4] = {v.x, v.y, v.z, v.w};
#pragma unroll
    for (int i = 0; i < 4; i++) {
        __half h1 = __float2half_rn(f[i]);
        __half h2 = __float2half_rn(f[i] - __half2float(h1));
        int k = t * 4 + i;
        g_ecat[c][k]       = h1;
        g_ecat[c][256 + k] = h2;
    }
    float s = v.x * v.x + v.y * v.y + v.z * v.z + v.w * v.w;
#pragma unroll
    for (int o = 16; o > 0; o >>= 1) s += __shfl_down_sync(0xffffffffu, s, o);
    __shared__ float sh[2];
    if ((t & 31) == 0) sh[t >> 5] = s;
    __syncthreads();
    if (t == 0) g_enorm[c] = sh[0] + sh[1];
}

// ---------------- prep: z NCHW -> rows + split ----------------
__global__ void __launch_bounds__(256) zprep_kernel(const float* __restrict__ ze) {
    __shared__ float zt[D][33];
    int b = blockIdx.x, hw0 = blockIdx.y * 32;
    int tid = threadIdx.x, w = tid >> 5, l = tid & 31;
    for (int k = w; k < D; k += 8)
        zt[k][l] = ze[((size_t)b * D + k) * HW + hw0 + l];
    __syncthreads();
    int r = tid >> 3, seg = tid & 7;
    int n = b * HW + hw0 + r;
#pragma unroll
    for (int i = 0; i < 32; i++) {
        int k = seg * 32 + i;
        float f = zt[k][r];
        __half h1 = __float2half_rn(f);
        __half h2 = __float2half_rn(f - __half2float(h1));
        g_zcat[n][k]       = h1;
        g_zcat[n][256 + k] = h2;
    }
}

// ---------------- main GEMM + argmin ----------------
__device__ __forceinline__ void mma16816(float d[4], uint32_t a0, uint32_t a1,
                                         uint32_t a2, uint32_t a3,
                                         uint32_t b0, uint32_t b1) {
    asm volatile(
        "mma.sync.aligned.m16n8k16.row.col.f32.f16.f16.f32 "
        "{%0,%1,%2,%3}, {%4,%5,%6,%7}, {%8,%9}, {%0,%1,%2,%3};"
        : "+f"(d[0]), "+f"(d[1]), "+f"(d[2]), "+f"(d[3])
        : "r"(a0), "r"(a1), "r"(a2), "r"(a3), "r"(b0), "r"(b1));
}

__device__ __forceinline__ void ldmatrix_x4(uint32_t& r0, uint32_t& r1,
                                            uint32_t& r2, uint32_t& r3,
                                            uint32_t addr) {
    asm volatile("ldmatrix.sync.aligned.m8n8.x4.shared.b16 {%0,%1,%2,%3}, [%4];"
                 : "=r"(r0), "=r"(r1), "=r"(r2), "=r"(r3) : "r"(addr));
}

// explicit shared-space 128-bit load (addr is a cvta.to.shared u32)
__device__ __forceinline__ void lds128(uint32_t& r0, uint32_t& r1,
                                       uint32_t& r2, uint32_t& r3,
                                       uint32_t addr) {
    asm volatile("ld.shared.v4.b32 {%0,%1,%2,%3}, [%4];"
                 : "=r"(r0), "=r"(r1), "=r"(r2), "=r"(r3) : "r"(addr));
}

__device__ __forceinline__ void cp16(void* dst, const void* src) {
    uint32_t d;
    asm("{ .reg .u64 t; cvta.to.shared.u64 t, %1; cvt.u32.u64 %0, t; }" : "=r"(d) : "l"(dst));
    asm volatile("cp.async.cg.shared.global [%0], [%1], 16;" :: "r"(d), "l"(src));
}
#define CP_COMMIT() asm volatile("cp.async.commit_group;" ::: "memory")
#define CP_WAIT(n)  asm volatile("cp.async.wait_group %0;" :: "n"(n) : "memory")

// B swizzled byte address: row n (256B), kb = byte offset in row (0..255, 16B units)
__device__ __forceinline__ uint32_t b_addr(int n, int kb) {
    return (uint32_t)(n * 256 + (kb & 0x8F) + ((((kb >> 4) & 7) ^ (n & 7)) << 4));
}

__device__ __forceinline__ uint32_t smem_u32(const void* p) {
    uint32_t a;
    asm("{ .reg .u64 t; cvta.to.shared.u64 t, %1; cvt.u32.u64 %0, t; }" : "=r"(a) : "l"(p));
    return a;
}

extern __shared__ char dsm[];

__global__ void __launch_bounds__(256, 1) vq_main(
    const float* __restrict__ cb, float* __restrict__ out, int Nq, int write_idx)
{
    __shared__ int s_bi[MT];

    char* As = dsm;                      // fragment-layout A, dedup [z1|z2]
    char* Bs = dsm + A_BYTES;            // three 32KB B slice buffers
    float* redv = reinterpret_cast<float*>(Bs);            // final reduce (reuse B)
    int*   redi = reinterpret_cast<int*>(Bs + MT * 8 * 4);

    const int tid = threadIdx.x;
    const int lane = tid & 31, w = tid >> 5;
    const int wm = w & 3, wn = w >> 2;   // 4 m-groups x 2 n-halves
    const int n0 = blockIdx.x * MT;
    const uint32_t Bs_u32 = smem_u32(Bs);

    // ldmatrix per-lane constants: matrix m = lane>>3, row = lane&7
    const int lm   = lane >> 3;
    const int row8 = lane & 7;
    const uint32_t lane_nbase = (uint32_t)((wn * 64 + ((lm >> 1) << 3) + row8) * 256);
    const uint32_t xor7  = (uint32_t)(row8 << 4);
    const uint32_t klane = (uint32_t)((lm & 1) << 4);

    // A fragment base SHARED-SPACE addresses for this warp (two m-tiles)
    const uint32_t As_u32 = smem_u32(As);
    const uint32_t a_base0 = As_u32 + (uint32_t)((((wm * 2 + 0) * 32) * 32 + lane) * 16);
    const uint32_t a_base1 = As_u32 + (uint32_t)((((wm * 2 + 1) * 32) * 32 + lane) * 16);

    // ---- build A fragments: A_frag[mt(8)][pkt(32)][lane(32)][4xb32]
    for (int i = tid; i < 8 * 32 * 32; i += 256) {
        int la = i & 31, pkt = (i >> 5) & 31, mt = (i >> 5) >> 5;
        int q  = n0 + mt * 16 + (la >> 2);
        int k0 = pkt * 16 + 2 * (la & 3);
        const char* zr = (const char*)&g_zcat[q][0];
        uint4 v;
        v.x = *(const uint32_t*)(zr + 2 * k0);
        v.y = *(const uint32_t*)(zr + 2 * k0 + 2 * 8 * KPHYS);      // row q+8
        v.z = *(const uint32_t*)(zr + 2 * (k0 + 8));
        v.w = *(const uint32_t*)(zr + 2 * (k0 + 8) + 2 * 8 * KPHYS);
        *reinterpret_cast<uint4*>(As + (size_t)i * 16) = v;
    }

    float acc[2][8][4];
    float bestv[4];
    int   besti[4];
#pragma unroll
    for (int i = 0; i < 4; i++) { bestv[i] = 3.0e38f; besti[i] = 0; }

    // logical slice s -> A physical slice, B k-offset in [e1|e2]
    const int a_ps[SLICES]   = {0, 1, 0, 1, 2, 3};
    const int b_koff[SLICES] = {0, 128, 256, 384, 0, 128};

    // ---- prologue: preload slices g=0 and g=1 into stages 0,1
#pragma unroll
    for (int pg = 0; pg < 2; pg++) {
        char* bd = Bs + pg * B_BYTES;
        const int ks = b_koff[pg];
#pragma unroll
        for (int j = 0; j < 8; j++) {
            int unit = tid + j * 256;
            int n = unit >> 4, u = unit & 15;
            cp16(bd + b_addr(n, u * 16), &g_ecat[n][ks + u * 8]);
        }
        CP_COMMIT();
    }

    int buf = 0, pbuf = 2;
    int s = 0, chunk = 0;
    int sn = 2, cn = 0;                  // slice/chunk of g+2

    for (int g = 0; g < GTOT; g++) {
        CP_WAIT(1);                      // group g complete
        __syncthreads();                 // g visible to all; all done with g-1

        if (g + 2 < GTOT) {              // prefetch g+2 into freed stage
            char* bd = Bs + pbuf * B_BYTES;
            const int c0n = cn * NT, ksn = b_koff[sn];
#pragma unroll
            for (int j = 0; j < 8; j++) {
                int unit = tid + j * 256;
                int n = unit >> 4, u = unit & 15;
                cp16(bd + b_addr(n, u * 16), &g_ecat[c0n + n][ksn + u * 8]);
            }
        }
        CP_COMMIT();

        if (s == 0) {
#pragma unroll
            for (int mt = 0; mt < 2; mt++)
#pragma unroll
                for (int nt = 0; nt < 8; nt++)
#pragma unroll
                    for (int e = 0; e < 4; e++) acc[mt][nt][e] = 0.f;
        }

        const uint32_t bbase = Bs_u32 + (uint32_t)buf * B_BYTES + lane_nbase;
        const uint32_t a_off = (uint32_t)(a_ps[s] * 8) * 512u;   // pkt stride = 512B

        // ---- software-pipelined fragment loop: load ktl+1 before mma(ktl)
        uint32_t Af0[2][4], Af1[2][4];
        uint32_t Bf[2][16];
        {
            const uint32_t off0 = (klane & 0x80u) | ((klane & 0x70u) ^ xor7);
            lds128(Af0[0][0], Af0[0][1], Af0[0][2], Af0[0][3], a_base0 + a_off);
            lds128(Af1[0][0], Af1[0][1], Af1[0][2], Af1[0][3], a_base1 + a_off);
#pragma unroll
            for (int ntp = 0; ntp < 4; ntp++)
                ldmatrix_x4(Bf[0][4*ntp], Bf[0][4*ntp+1], Bf[0][4*ntp+2], Bf[0][4*ntp+3],
                            bbase + (uint32_t)(ntp * 4096) + off0);
        }
#pragma unroll
        for (int ktl = 0; ktl < 8; ktl++) {
            const int cur = ktl & 1, nxt = cur ^ 1;
            if (ktl < 7) {
                const uint32_t kbn = (uint32_t)((ktl + 1) * 32) + klane;
                const uint32_t offn = (kbn & 0x80u) | ((kbn & 0x70u) ^ xor7);
                const uint32_t a_k = a_off + (uint32_t)(ktl + 1) * 512u;
                lds128(Af0[nxt][0], Af0[nxt][1], Af0[nxt][2], Af0[nxt][3], a_base0 + a_k);
                lds128(Af1[nxt][0], Af1[nxt][1], Af1[nxt][2], Af1[nxt][3], a_base1 + a_k);
#pragma unroll
                for (int ntp = 0; ntp < 4; ntp++)
                    ldmatrix_x4(Bf[nxt][4*ntp], Bf[nxt][4*ntp+1],
                                Bf[nxt][4*ntp+2], Bf[nxt][4*ntp+3],
                                bbase + (uint32_t)(ntp * 4096) + offn);
            }
#pragma unroll
            for (int ntp = 0; ntp < 4; ntp++) {
                mma16816(acc[0][2*ntp],     Af0[cur][0], Af0[cur][1], Af0[cur][2], Af0[cur][3],
                         Bf[cur][4*ntp],   Bf[cur][4*ntp+1]);
                mma16816(acc[1][2*ntp],     Af1[cur][0], Af1[cur][1], Af1[cur][2], Af1[cur][3],
                         Bf[cur][4*ntp],   Bf[cur][4*ntp+1]);
                mma16816(acc[0][2*ntp + 1], Af0[cur][0], Af0[cur][1], Af0[cur][2], Af0[cur][3],
                         Bf[cur][4*ntp+2], Bf[cur][4*ntp+3]);
                mma16816(acc[1][2*ntp + 1], Af1[cur][0], Af1[cur][1], Af1[cur][2], Af1[cur][3],
                         Bf[cur][4*ntp+2], Bf[cur][4*ntp+3]);
            }
        }

        if (s == SLICES - 1) {
            // fold chunk scores into running argmin (ascending index order)
            const int c0 = chunk * NT + wn * 64 + 2 * (lane & 3);
#pragma unroll
            for (int mt = 0; mt < 2; mt++)
#pragma unroll
                for (int nt = 0; nt < 8; nt++) {
                    int cb0 = c0 + nt * 8;
                    float en0 = __ldg(&g_enorm[cb0]);
                    float en1 = __ldg(&g_enorm[cb0 + 1]);
                    float s0 = fmaf(-2.0f, acc[mt][nt][0], en0);
                    float s1 = fmaf(-2.0f, acc[mt][nt][1], en1);
                    float s2 = fmaf(-2.0f, acc[mt][nt][2], en0);
                    float s3 = fmaf(-2.0f, acc[mt][nt][3], en1);
                    int blo = mt * 2, bhi = mt * 2 + 1;
                    if (s0 < bestv[blo]) { bestv[blo] = s0; besti[blo] = cb0; }
                    if (s1 < bestv[blo]) { bestv[blo] = s1; besti[blo] = cb0 + 1; }
                    if (s2 < bestv[bhi]) { bestv[bhi] = s2; besti[bhi] = cb0; }
                    if (s3 < bestv[bhi]) { bestv[bhi] = s3; besti[bhi] = cb0 + 1; }
                }
        }

        buf  = (buf  == STAGES - 1) ? 0 : buf + 1;
        pbuf = (pbuf == STAGES - 1) ? 0 : pbuf + 1;
        if (++s == SLICES) { s = 0; chunk++; }
        if (++sn == SLICES) { sn = 0; cn++; }
    }

    // ---- final cross-thread argmin reduction (lexicographic, first occurrence)
    __syncthreads();
#pragma unroll
    for (int bq = 0; bq < 4; bq++) {
        int q = wm * 32 + (bq >> 1) * 16 + (bq & 1) * 8 + (lane >> 2);
        int slot = wn * 4 + (lane & 3);
        redv[q * 8 + slot] = bestv[bq];
        redi[q * 8 + slot] = besti[bq];
    }
    __syncthreads();
    if (tid < MT) {
        float bv = redv[tid * 8];
        int   bx = redi[tid * 8];
#pragma unroll
        for (int t = 1; t < 8; t++) {
            float v  = redv[tid * 8 + t];
            int   ix = redi[tid * 8 + t];
            if (v < bv || (v == bv && ix < bx)) { bv = v; bx = ix; }
        }
        s_bi[tid] = bx;
        if (write_idx) out[(size_t)Nq * D + n0 + tid] = (float)bx;
    }
    __syncthreads();

    // ---- gather z_q rows from original fp32 codebook
    const float4* cb4 = reinterpret_cast<const float4*>(cb);
    float4* out4 = reinterpret_cast<float4*>(out);
    for (int e = tid; e < MT * (D / 4); e += 256) {
        int q = e >> 6, p = e & 63;
        out4[(size_t)(n0 + q) * (D / 4) + p] = cb4[(size_t)s_bi[q] * (D / 4) + p];
    }
}

extern "C" void kernel_launch(void* const* d_in, const int* in_sizes, int n_in,
                              void* d_out, int out_size) {
    const float* ze = (const float*)d_in[0];
    const float* cb = (const float*)d_in[1];
    float* out = (float*)d_out;

    int Nq = in_sizes[0] / D;                 // 16384
    int nb = Nq / HW;                         // 16
    int write_idx = (out_size >= Nq * D + Nq) ? 1 : 0;

    cudaFuncSetAttribute(vq_main, cudaFuncAttributeMaxDynamicSharedMemorySize, DYN_SMEM);

    eprep_kernel<<<BOOK, 64>>>(cb);
    zprep_kernel<<<dim3(nb, 32), 256>>>(ze);
    vq_main<<<Nq / MT, 256, DYN_SMEM>>>(cb, out, Nq, write_idx);
}